// round 2
// baseline (speedup 1.0000x reference)
#include <cuda_runtime.h>
#include <math.h>
#include <stdint.h>

// Problem constants (fixed by the seeded reference):
//   m=8, nc=1024, nt=512, dim=2, dy=2, PPU=64 -> grid 129x129 per batch.
#define M_B   8
#define NC    1024
#define NT    512
#define AX    129
#define NG    (AX * AX)            // 16641
#define HALF  64
#define INV_PPU (1.0f / 64.0f)
#define X_TOTAL (M_B * NG * 2)     // x_grid floats, then z_grid

#define WXROW 132                  // i-dim padded to 132 (zeros beyond 128)
#define KC    128                  // contexts per smem chunk
#define NCH   (NC / KC)            // 8
#define JT    8                    // j columns per CTA
#define NJT   17                   // ceil(129/8)

#define SWX_BYTES  (KC * WXROW * 4)   // 67584
#define SWYY_BYTES (KC * JT * 32)     // 32768
#define BUF_BYTES  (SWX_BYTES + SWYY_BYTES)  // 100352
#define SMEM_TOTAL (2 * BUF_BYTES)           // 200704

// Scratch (no allocations allowed)
__device__ float  g_wx[M_B * NC * WXROW];       // 4.3 MB   [b][c][i]
__device__ float  g_wyy[M_B * NC * AX * 8];     // 33.8 MB  [b][c][j][{y0,y0,y1,y1,w,w,0,0}]
__device__ float2 g_mid[M_B];

__device__ __forceinline__ float ex2f(float x) {
    float r; asm("ex2.approx.f32 %0, %1;" : "=f"(r) : "f"(x)); return r;
}
__device__ __forceinline__ float soft_k(float p) {
    // weight = 2^(-((dx*k)^2)) with k = sqrt(0.5*log2(e)) / (1e-5 + softplus(p))
    float ls = 1e-5f + log1pf(expf(p));
    return sqrtf(0.5f * 1.44269504088896341f) / ls;
}
__device__ __forceinline__ uint32_t smem_addr_u32(const void* p) {
    uint32_t a;
    asm("{ .reg .u64 t; cvta.to.shared.u64 t, %1; cvt.u32.u64 %0, t; }" : "=r"(a) : "l"(p));
    return a;
}
__device__ __forceinline__ void cpasync16(uint32_t dst, const void* src) {
    asm volatile("cp.async.ca.shared.global [%0], [%1], 16;" :: "r"(dst), "l"(src));
}
#define FMA2(acc, a, b) \
    asm("fma.rn.f32x2 %0, %1, %2, %0;" : "+l"(acc) : "l"(a), "l"(b))

// ---------------- Kernel 1: per-batch min/max -> grid midpoint ----------------
__global__ void __launch_bounds__(256) prep_kernel(const float* __restrict__ xc,
                                                   const float* __restrict__ xt) {
    const int b = blockIdx.x;
    const int t = threadIdx.x;
    const float* xb = xc + b * NC * 2;
    const float* tb = xt + b * NT * 2;

    float mn0 = 1e30f, mx0 = -1e30f, mn1 = 1e30f, mx1 = -1e30f;
    for (int i = t; i < NC; i += 256) {
        float a = xb[2 * i], c = xb[2 * i + 1];
        mn0 = fminf(mn0, a); mx0 = fmaxf(mx0, a);
        mn1 = fminf(mn1, c); mx1 = fmaxf(mx1, c);
    }
    for (int i = t; i < NT; i += 256) {
        float a = tb[2 * i], c = tb[2 * i + 1];
        mn0 = fminf(mn0, a); mx0 = fmaxf(mx0, a);
        mn1 = fminf(mn1, c); mx1 = fmaxf(mx1, c);
    }
    for (int o = 16; o; o >>= 1) {
        mn0 = fminf(mn0, __shfl_xor_sync(0xffffffffu, mn0, o));
        mx0 = fmaxf(mx0, __shfl_xor_sync(0xffffffffu, mx0, o));
        mn1 = fminf(mn1, __shfl_xor_sync(0xffffffffu, mn1, o));
        mx1 = fmaxf(mx1, __shfl_xor_sync(0xffffffffu, mx1, o));
    }
    __shared__ float s[4][8];
    const int lane = t & 31, wid = t >> 5;
    if (lane == 0) { s[0][wid] = mn0; s[1][wid] = mx0; s[2][wid] = mn1; s[3][wid] = mx1; }
    __syncthreads();
    if (t == 0) {
        float a = s[0][0], bb = s[1][0], c = s[2][0], d = s[3][0];
        #pragma unroll
        for (int w = 1; w < 8; w++) {
            a = fminf(a, s[0][w]); bb = fmaxf(bb, s[1][w]);
            c = fminf(c, s[2][w]); d = fmaxf(d, s[3][w]);
        }
        g_mid[b] = make_float2(0.5f * (a + bb), 0.5f * (c + d));
    }
}

// ------------- Kernel 2: fill separable factor tables wx / wyy -------------
__global__ void __launch_bounds__(256) fill_kernel(const float* __restrict__ xc,
                                                   const float* __restrict__ yc,
                                                   const float* __restrict__ lsp) {
    const int w = blockIdx.x * 8 + (threadIdx.x >> 5);
    const int lane = threadIdx.x & 31;
    const int b = w >> 10;
    const int c = w & 1023;
    const float k0 = soft_k(lsp[0]);
    const float k1 = soft_k(lsp[1]);
    const float2 mid = g_mid[b];
    const float vx = xc[(b * NC + c) * 2], vy = xc[(b * NC + c) * 2 + 1];
    const float y0 = yc[(b * NC + c) * 2], y1 = yc[(b * NC + c) * 2 + 1];

    float* wxrow = g_wx + (size_t)(b * NC + c) * WXROW;
    float4* wyrow = (float4*)(g_wyy + (size_t)(b * NC + c) * AX * 8);

    for (int i = lane; i < WXROW; i += 32) {
        float gx = mid.x + (float)(i - HALF) * INV_PPU;
        float d = (gx - vx) * k0;
        wxrow[i] = (i < AX) ? ex2f(-d * d) : 0.0f;
    }
    for (int j = lane; j < AX; j += 32) {
        float gy = mid.y + (float)(j - HALF) * INV_PPU;
        float d = (gy - vy) * k1;
        float wv = ex2f(-d * d);
        wyrow[2 * j + 0] = make_float4(wv * y0, wv * y0, wv * y1, wv * y1);
        wyrow[2 * j + 1] = make_float4(wv, wv, 0.0f, 0.0f);
    }
}

// ------------- Kernel 3: batched fp32 "GEMM" Z = wx^T * wyy + x_grid -------------
extern __shared__ char dynsmem[];

__global__ void __launch_bounds__(256) gemm_kernel(float* __restrict__ out) {
    const int b   = blockIdx.y;
    const int jt  = blockIdx.x;
    const int tid = threadIdx.x;
    const int iq  = tid & 31;        // i-quad: i = 4*iq .. 4*iq+3  (i < 128)
    const int jj  = tid >> 5;        // 0..7
    const int j   = jt * JT + jj;

    const uint32_t smem = smem_addr_u32(dynsmem);
    const float* gwx = g_wx + (size_t)b * NC * WXROW;

    // --- async stage of one K-chunk into buffer (chunk & 1) ---
    auto stage = [&](int chunk) {
        const int c0 = chunk * KC;
        const uint32_t base = smem + (chunk & 1) * BUF_BYTES;
        const float4* src = (const float4*)(gwx + (size_t)c0 * WXROW);
        for (int idx = tid; idx < KC * WXROW / 4; idx += 256)
            cpasync16(base + idx * 16, src + idx);
        const uint32_t wyb = base + SWX_BYTES;
        for (int idx = tid; idx < KC * JT * 2; idx += 256) {
            int cc = idx >> 4; int rem = idx & 15; int jjj = rem >> 1; int half = rem & 1;
            int jl = jt * JT + jjj; if (jl >= AX) jl = AX - 1;
            const float4* s = (const float4*)(g_wyy + ((size_t)(b * NC + c0 + cc) * AX + jl) * 8) + half;
            cpasync16(wyb + (cc * JT + jjj) * 32 + half * 16, s);
        }
        asm volatile("cp.async.commit_group;" ::: "memory");
    };

    unsigned long long a0a = 0, a0b = 0, a1a = 0, a1b = 0, a2a = 0, a2b = 0;
    unsigned long long e0 = 0, e1 = 0, e2 = 0;   // i = 128 row (broadcast-redundant)

    stage(0);
    for (int ch = 0; ch < NCH; ch++) {
        if (ch + 1 < NCH) {
            stage(ch + 1);
            asm volatile("cp.async.wait_group 1;" ::: "memory");
        } else {
            asm volatile("cp.async.wait_group 0;" ::: "memory");
        }
        __syncthreads();
        const uint32_t base = smem + (ch & 1) * BUF_BYTES;
        const uint32_t wxa  = base + iq * 16;
        const uint32_t wya  = base + SWX_BYTES + jj * 32;
        #pragma unroll 4
        for (int kk = 0; kk < KC; kk++) {
            unsigned long long w01, w23, y00, y11, y22, w45;
            asm("ld.shared.v2.u64 {%0,%1}, [%2];" : "=l"(w01), "=l"(w23) : "r"(wxa + kk * 528));
            asm("ld.shared.v2.u64 {%0,%1}, [%2];" : "=l"(y00), "=l"(y11) : "r"(wya + kk * 256));
            asm("ld.shared.u64 %0, [%1];" : "=l"(y22) : "r"(wya + kk * 256 + 16));
            asm("ld.shared.u64 %0, [%1];" : "=l"(w45) : "r"(base + kk * 528 + 512));
            FMA2(a0a, w01, y00); FMA2(a0b, w23, y00);
            FMA2(a1a, w01, y11); FMA2(a1b, w23, y11);
            FMA2(a2a, w01, y22); FMA2(a2b, w23, y22);
            FMA2(e0,  w45, y00); FMA2(e1,  w45, y11); FMA2(e2,  w45, y22);
        }
        __syncthreads();
    }

    if (j < AX) {
        union { unsigned long long u; float f[2]; } v;
        const int i0 = 4 * iq;
        const size_t zb = (size_t)X_TOTAL + ((size_t)b * NG + (size_t)i0 * AX + j) * 3;
        const size_t R = 3 * AX;  // 387: stride between consecutive i rows
        v.u = a0a; out[zb + 0]         = v.f[0]; out[zb + R + 0]     = v.f[1];
        v.u = a0b; out[zb + 2 * R + 0] = v.f[0]; out[zb + 3 * R + 0] = v.f[1];
        v.u = a1a; out[zb + 1]         = v.f[0]; out[zb + R + 1]     = v.f[1];
        v.u = a1b; out[zb + 2 * R + 1] = v.f[0]; out[zb + 3 * R + 1] = v.f[1];
        v.u = a2a; out[zb + 2]         = v.f[0]; out[zb + R + 2]     = v.f[1];
        v.u = a2b; out[zb + 2 * R + 2] = v.f[0]; out[zb + 3 * R + 2] = v.f[1];

        // x_grid for this thread's 4 rows at column j (bit-exact forms)
        const float2 mid = g_mid[b];
        const float gy = mid.y + (float)(j - HALF) * INV_PPU;
        #pragma unroll
        for (int ii = 0; ii < 4; ii++) {
            const float gx = mid.x + (float)(i0 + ii - HALF) * INV_PPU;
            float* xg = out + ((size_t)b * NG + (size_t)(i0 + ii) * AX + j) * 2;
            xg[0] = gx; xg[1] = gy;
        }
        if (iq == 0) {  // i = 128 row
            const size_t eb = (size_t)X_TOTAL + ((size_t)b * NG + (size_t)128 * AX + j) * 3;
            v.u = e0; out[eb + 0] = v.f[0];
            v.u = e1; out[eb + 1] = v.f[0];
            v.u = e2; out[eb + 2] = v.f[0];
            const float gx = mid.x + (float)(128 - HALF) * INV_PPU;
            float* xg = out + ((size_t)b * NG + (size_t)128 * AX + j) * 2;
            xg[0] = gx; xg[1] = gy;
        }
    }
}

extern "C" void kernel_launch(void* const* d_in, const int* in_sizes, int n_in,
                              void* d_out, int out_size) {
    const float* xc  = (const float*)d_in[0];
    const float* yc  = (const float*)d_in[1];
    const float* xt  = (const float*)d_in[2];
    const float* lsp = (const float*)d_in[3];
    float* out = (float*)d_out;

    cudaFuncSetAttribute(gemm_kernel, cudaFuncAttributeMaxDynamicSharedMemorySize, SMEM_TOTAL);

    prep_kernel<<<M_B, 256>>>(xc, xt);
    fill_kernel<<<(M_B * NC) / 8, 256>>>(xc, yc, lsp);
    dim3 grid(NJT, M_B);
    gemm_kernel<<<grid, 256, SMEM_TOTAL>>>(out);
}